// round 13
// baseline (speedup 1.0000x reference)
#include <cuda_runtime.h>
#include <cstdint>

#define BB 4
#define CC 256
#define HH 56
#define WW 56
#define CR 64          // C / 4
#define GG 16          // groups
#define GC 16
#define KK 7
#define K2T 49
#define M2 784         // GG * K2T
#define HW 3136        // HH * WW
#define PAD 3
#define N1 (BB * CR * HW)   // 802816

// ---- fused K2+K3 smem layout (floats) --------------------------------------
#define PXT 112                       // 2 rows x 56 px per block
#define XS_F (GC * 8 * 64)            // 8192  : x tile, rows h0-3..h0+4, +3 shift
#define W1S_F (CR * PXT)              // 7168  : w1 slice [k][p]
#define CW_F (K2T * CR)               // 3136  : conv2 weights for group
#define BIAS_F 64                     // 49 used
#define WS_F (K2T * PXT)              // 5488  : per-pixel kernels [tap][p]
#define OFF_XS 0
#define OFF_W1S (OFF_XS + XS_F)
#define OFF_CW (OFF_W1S + W1S_F)
#define OFF_BIAS (OFF_CW + CW_F)
#define OFF_WS (OFF_BIAS + BIAS_F)
#define K23_SMEM_BYTES ((OFF_WS + WS_F) * 4)   // 96192 B -> 2 blocks/SM

// Scratch (__device__ globals; no allocations allowed)
__device__ float g_p[2 * N1];               // K1 split-K partials
__device__ float g_w1[N1];                  // [B, Cr, HW]

// ---------------------------------------------------------------------------
// K1a: partial conv1 over half the C range (split-K = 2). (round-8, unchanged)
// ---------------------------------------------------------------------------
__global__ __launch_bounds__(128) void k1a_partial(
        const float* __restrict__ x,
        const float* __restrict__ w1w) {
    __shared__ float As[64 * 68];    // [k][o]
    __shared__ float Bs[64 * 32];    // [k][px]

    const int tid = threadIdx.x;
    const int tx = tid & 7;
    const int ty = tid >> 3;
    const int px0 = blockIdx.x * 32;
    const int b = blockIdx.y;
    const int ks = blockIdx.z;

    float acc[4][4];
#pragma unroll
    for (int i = 0; i < 4; ++i)
#pragma unroll
        for (int u = 0; u < 4; ++u) acc[i][u] = 0.f;

    for (int kt = ks * 128; kt < ks * 128 + 128; kt += 64) {
        {
            int k = tid & 63;
            int oh = tid >> 6;
#pragma unroll
            for (int r = 0; r < 32; ++r) {
                int o = 2 * r + oh;
                As[k * 68 + o] = w1w[o * CC + kt + k];
            }
        }
        {
            int j = tid & 31;
            int kh = tid >> 5;
#pragma unroll
            for (int r = 0; r < 16; ++r) {
                int k = 4 * r + kh;
                Bs[k * 32 + j] = x[(size_t)(b * CC + kt + k) * HW + px0 + j];
            }
        }
        __syncthreads();

#pragma unroll 16
        for (int k = 0; k < 64; ++k) {
            float4 av = *(const float4*)&As[k * 68 + ty * 4];
            float4 bv = *(const float4*)&Bs[k * 32 + tx * 4];
            acc[0][0] = fmaf(av.x, bv.x, acc[0][0]);
            acc[0][1] = fmaf(av.x, bv.y, acc[0][1]);
            acc[0][2] = fmaf(av.x, bv.z, acc[0][2]);
            acc[0][3] = fmaf(av.x, bv.w, acc[0][3]);
            acc[1][0] = fmaf(av.y, bv.x, acc[1][0]);
            acc[1][1] = fmaf(av.y, bv.y, acc[1][1]);
            acc[1][2] = fmaf(av.y, bv.z, acc[1][2]);
            acc[1][3] = fmaf(av.y, bv.w, acc[1][3]);
            acc[2][0] = fmaf(av.z, bv.x, acc[2][0]);
            acc[2][1] = fmaf(av.z, bv.y, acc[2][1]);
            acc[2][2] = fmaf(av.z, bv.z, acc[2][2]);
            acc[2][3] = fmaf(av.z, bv.w, acc[2][3]);
            acc[3][0] = fmaf(av.w, bv.x, acc[3][0]);
            acc[3][1] = fmaf(av.w, bv.y, acc[3][1]);
            acc[3][2] = fmaf(av.w, bv.z, acc[3][2]);
            acc[3][3] = fmaf(av.w, bv.w, acc[3][3]);
        }
        __syncthreads();
    }

#pragma unroll
    for (int i = 0; i < 4; ++i) {
        int o = ty * 4 + i;
        float4 v = make_float4(acc[i][0], acc[i][1], acc[i][2], acc[i][3]);
        *(float4*)(g_p + (size_t)ks * N1 + (size_t)(b * CR + o) * HW
                   + px0 + tx * 4) = v;
    }
}

// ---------------------------------------------------------------------------
// K1b: sum partials + BN(eval) + ReLU. (round-8, unchanged)
// ---------------------------------------------------------------------------
__global__ __launch_bounds__(256) void k1b_bn_relu(
        const float* __restrict__ gamma,
        const float* __restrict__ beta,
        const float* __restrict__ mean,
        const float* __restrict__ var) {
    int i4 = blockIdx.x * blockDim.x + threadIdx.x;
    if (i4 >= N1 / 4) return;
    int idx = i4 * 4;
    int o = (idx / HW) % CR;

    float sc = gamma[o] * rsqrtf(var[o] + 1e-5f);
    float sh = beta[o] - mean[o] * sc;

    float4 p0 = *(const float4*)(g_p + idx);
    float4 p1 = *(const float4*)(g_p + N1 + idx);
    float4 v;
    v.x = fmaxf(fmaf(p0.x + p1.x, sc, sh), 0.f);
    v.y = fmaxf(fmaf(p0.y + p1.y, sc, sh), 0.f);
    v.z = fmaxf(fmaf(p0.z + p1.z, sc, sh), 0.f);
    v.w = fmaxf(fmaf(p0.w + p1.w, sc, sh), 0.f);
    *(float4*)(g_w1 + idx) = v;
}

// ---------------------------------------------------------------------------
// K23: fused conv2 + involution. Block = (2-row band, group, batch).
// Phase 1: stage w1 slice [64][112], conv2 weights [49][64], bias, x window.
// Phase 2: mini-GEMM ws[49][112] = cw x w1s + bias   (the w2 slice, in smem).
// Phase 3: involution reduce from ws + xs. No g_w2 gmem traffic at all.
// ---------------------------------------------------------------------------
__global__ __launch_bounds__(256) void k23_fused(
        const float* __restrict__ x,
        const float* __restrict__ w2w,
        const float* __restrict__ w2b,
        float* __restrict__ out) {
    extern __shared__ float sm[];
    float* xs  = sm + OFF_XS;    // [16ch][8rows][64(+3 shift)]
    float* w1s = sm + OFF_W1S;   // [64k][112px]
    float* cw  = sm + OFF_CW;    // [49tap][64k]
    float* bs  = sm + OFF_BIAS;  // [49]
    float* ws  = sm + OFF_WS;    // [49tap][112px]

    const int tid = threadIdx.x;
    const int h0 = blockIdx.x * 2;
    const int g = blockIdx.y;
    const int b = blockIdx.z;

    // ---- Phase 1: staging (all coalesced) ----
    {   // w1 slice: rows k, 112 contiguous px starting at h0*56
        const float* src = g_w1 + (size_t)b * CR * HW + h0 * WW;
        for (int i = tid; i < CR * 28; i += 256) {      // 1792 float4
            int k = i / 28, q = i - (i / 28) * 28;
            *(float4*)&w1s[k * PXT + q * 4] =
                *(const float4*)(src + (size_t)k * HW + q * 4);
        }
    }
    {   // conv2 weights for this group: rows g*49..g*49+48 contiguous
        const float* src = w2w + (size_t)g * K2T * CR;
        for (int i = tid; i < (K2T * CR) / 4; i += 256) // 784 float4
            *(float4*)&cw[i * 4] = *(const float4*)(src + i * 4);
    }
    if (tid < K2T) bs[tid] = w2b[g * K2T + tid];
    {   // x window: rows h0-3..h0+4, cols -3..60 (clipped)
        const float* xg = x + (size_t)(b * CC + g * GC) * HW;
        for (int i = tid; i < XS_F; i += 256) {
            int ch = i >> 9;
            int rem = i & 511;
            int rr = rem >> 6;
            int c = rem & 63;
            int hh = h0 - 3 + rr;
            int wc = c - 3;
            float v = 0.f;
            if (hh >= 0 && hh < HH && wc >= 0 && wc < WW)
                v = xg[(size_t)ch * HW + hh * WW + wc];
            xs[i] = v;
        }
    }
    __syncthreads();

    // ---- Phase 2: ws[tap][p] = bias[tap] + sum_k cw[tap][k] * w1s[k][p] ----
    if (tid < 196) {
        const int tq = tid % 28;         // px quad
        const int tg = tid / 28;         // tap group (7 taps)
        float acc[7][4];
#pragma unroll
        for (int i = 0; i < 7; ++i) {
            float bv = bs[tg * 7 + i];
#pragma unroll
            for (int u = 0; u < 4; ++u) acc[i][u] = bv;
        }
#pragma unroll 8
        for (int k = 0; k < CR; ++k) {
            float4 bv = *(const float4*)&w1s[k * PXT + tq * 4];
#pragma unroll
            for (int i = 0; i < 7; ++i) {
                float a = cw[(tg * 7 + i) * CR + k];
                acc[i][0] = fmaf(a, bv.x, acc[i][0]);
                acc[i][1] = fmaf(a, bv.y, acc[i][1]);
                acc[i][2] = fmaf(a, bv.z, acc[i][2]);
                acc[i][3] = fmaf(a, bv.w, acc[i][3]);
            }
        }
#pragma unroll
        for (int i = 0; i < 7; ++i)
            *(float4*)&ws[(tg * 7 + i) * PXT + tq * 4] =
                make_float4(acc[i][0], acc[i][1], acc[i][2], acc[i][3]);
    }
    __syncthreads();

    // ---- Phase 3: involution reduce from smem ----
    if (tid < 224) {
        const int q = tid % 28;          // 2 rows x 14 quads
        const int cg = tid / 28;         // 0..7 -> channel pair
        const int r = q / 14;
        const int qq = q - r * 14;
        const int w0 = qq * 4;

        float acc[2][4];
#pragma unroll
        for (int c = 0; c < 2; ++c)
#pragma unroll
            for (int p = 0; p < 4; ++p) acc[c][p] = 0.f;

#pragma unroll
        for (int ki = 0; ki < KK; ++ki) {
            float4 wv[7];
#pragma unroll
            for (int kj = 0; kj < KK; ++kj)
                wv[kj] = *(const float4*)&ws[(ki * KK + kj) * PXT + r * 56 + w0];
#pragma unroll
            for (int c = 0; c < 2; ++c) {
                const float* xr = &xs[(cg * 2 + c) * 512 + (r + ki) * 64 + w0];
                float4 xa = *(const float4*)(xr);
                float4 xb = *(const float4*)(xr + 4);
                float4 xc = *(const float4*)(xr + 8);
                float xw[12] = {xa.x, xa.y, xa.z, xa.w,
                                xb.x, xb.y, xb.z, xb.w,
                                xc.x, xc.y, xc.z, xc.w};
#pragma unroll
                for (int kj = 0; kj < KK; ++kj) {
                    acc[c][0] = fmaf(wv[kj].x, xw[kj + 0], acc[c][0]);
                    acc[c][1] = fmaf(wv[kj].y, xw[kj + 1], acc[c][1]);
                    acc[c][2] = fmaf(wv[kj].z, xw[kj + 2], acc[c][2]);
                    acc[c][3] = fmaf(wv[kj].w, xw[kj + 3], acc[c][3]);
                }
            }
        }

        const int h = h0 + r;
#pragma unroll
        for (int c = 0; c < 2; ++c) {
            float4 v = make_float4(acc[c][0], acc[c][1], acc[c][2], acc[c][3]);
            *(float4*)(out + (size_t)(b * CC + g * GC + cg * 2 + c) * HW
                       + h * WW + w0) = v;
        }
    }
}

// ---------------------------------------------------------------------------
extern "C" void kernel_launch(void* const* d_in, const int* in_sizes, int n_in,
                              void* d_out, int out_size) {
    const float* x     = (const float*)d_in[0];
    const float* w1w   = (const float*)d_in[1];
    const float* gamma = (const float*)d_in[2];
    const float* beta  = (const float*)d_in[3];
    const float* mean  = (const float*)d_in[4];
    const float* var   = (const float*)d_in[5];
    const float* w2w   = (const float*)d_in[6];
    const float* w2b   = (const float*)d_in[7];
    float* out = (float*)d_out;

    static bool attr_set = false;
    if (!attr_set) {
        cudaFuncSetAttribute(k23_fused,
                             cudaFuncAttributeMaxDynamicSharedMemorySize,
                             K23_SMEM_BYTES);
        attr_set = true;
    }

    dim3 g1(HW / 32, BB, 2);                    // 98 x 4 x 2 = 784
    k1a_partial<<<g1, 128>>>(x, w1w);

    k1b_bn_relu<<<(N1 / 4 + 255) / 256, 256>>>(gamma, beta, mean, var);

    dim3 g23(HH / 2, GG, BB);                   // 28 x 16 x 4 = 1792
    k23_fused<<<g23, 256, K23_SMEM_BYTES>>>(x, w2w, w2b, out);
}

// round 14
// speedup vs baseline: 1.1302x; 1.1302x over previous
#include <cuda_runtime.h>
#include <cstdint>

#define BB 4
#define CC 256
#define HH 56
#define WW 56
#define CR 64          // C / 4
#define GG 16          // groups
#define GC 16
#define KK 7
#define K2T 49
#define M2 784         // GG * K2T
#define HW 3136        // HH * WW
#define PAD 3
#define N1 (BB * CR * HW)   // 802816

// K3 smem: x tile [14 rows][16 ch][64 cols(+3 shift)] = 14336 floats (56KB)
#define XS_FLOATS (14 * 16 * 64)
#define K3_SMEM_BYTES (XS_FLOATS * 4)

// Scratch (__device__ globals; no allocations allowed)
__device__ float g_p[2 * N1];               // K1 split-K partials
__device__ float g_w1[N1];                  // [B, Cr, HW]
__device__ float g_w2[BB * M2 * HW];        // [B, G*49, HW]

// ---------------------------------------------------------------------------
// K1a: partial conv1 over half the C range (split-K = 2). (round-8, unchanged)
// ---------------------------------------------------------------------------
__global__ __launch_bounds__(128) void k1a_partial(
        const float* __restrict__ x,
        const float* __restrict__ w1w) {
    __shared__ float As[64 * 68];    // [k][o]
    __shared__ float Bs[64 * 32];    // [k][px]

    const int tid = threadIdx.x;
    const int tx = tid & 7;
    const int ty = tid >> 3;
    const int px0 = blockIdx.x * 32;
    const int b = blockIdx.y;
    const int ks = blockIdx.z;

    float acc[4][4];
#pragma unroll
    for (int i = 0; i < 4; ++i)
#pragma unroll
        for (int u = 0; u < 4; ++u) acc[i][u] = 0.f;

    for (int kt = ks * 128; kt < ks * 128 + 128; kt += 64) {
        {
            int k = tid & 63;
            int oh = tid >> 6;
#pragma unroll
            for (int r = 0; r < 32; ++r) {
                int o = 2 * r + oh;
                As[k * 68 + o] = w1w[o * CC + kt + k];
            }
        }
        {
            int j = tid & 31;
            int kh = tid >> 5;
#pragma unroll
            for (int r = 0; r < 16; ++r) {
                int k = 4 * r + kh;
                Bs[k * 32 + j] = x[(size_t)(b * CC + kt + k) * HW + px0 + j];
            }
        }
        __syncthreads();

#pragma unroll 16
        for (int k = 0; k < 64; ++k) {
            float4 av = *(const float4*)&As[k * 68 + ty * 4];
            float4 bv = *(const float4*)&Bs[k * 32 + tx * 4];
            acc[0][0] = fmaf(av.x, bv.x, acc[0][0]);
            acc[0][1] = fmaf(av.x, bv.y, acc[0][1]);
            acc[0][2] = fmaf(av.x, bv.z, acc[0][2]);
            acc[0][3] = fmaf(av.x, bv.w, acc[0][3]);
            acc[1][0] = fmaf(av.y, bv.x, acc[1][0]);
            acc[1][1] = fmaf(av.y, bv.y, acc[1][1]);
            acc[1][2] = fmaf(av.y, bv.z, acc[1][2]);
            acc[1][3] = fmaf(av.y, bv.w, acc[1][3]);
            acc[2][0] = fmaf(av.z, bv.x, acc[2][0]);
            acc[2][1] = fmaf(av.z, bv.y, acc[2][1]);
            acc[2][2] = fmaf(av.z, bv.z, acc[2][2]);
            acc[2][3] = fmaf(av.z, bv.w, acc[2][3]);
            acc[3][0] = fmaf(av.w, bv.x, acc[3][0]);
            acc[3][1] = fmaf(av.w, bv.y, acc[3][1]);
            acc[3][2] = fmaf(av.w, bv.z, acc[3][2]);
            acc[3][3] = fmaf(av.w, bv.w, acc[3][3]);
        }
        __syncthreads();
    }

#pragma unroll
    for (int i = 0; i < 4; ++i) {
        int o = ty * 4 + i;
        float4 v = make_float4(acc[i][0], acc[i][1], acc[i][2], acc[i][3]);
        *(float4*)(g_p + (size_t)ks * N1 + (size_t)(b * CR + o) * HW
                   + px0 + tx * 4) = v;
    }
}

// ---------------------------------------------------------------------------
// K1b: sum partials + BN(eval) + ReLU. (round-8, unchanged)
// ---------------------------------------------------------------------------
__global__ __launch_bounds__(256) void k1b_bn_relu(
        const float* __restrict__ gamma,
        const float* __restrict__ beta,
        const float* __restrict__ mean,
        const float* __restrict__ var) {
    int i4 = blockIdx.x * blockDim.x + threadIdx.x;
    if (i4 >= N1 / 4) return;
    int idx = i4 * 4;
    int o = (idx / HW) % CR;

    float sc = gamma[o] * rsqrtf(var[o] + 1e-5f);
    float sh = beta[o] - mean[o] * sc;

    float4 p0 = *(const float4*)(g_p + idx);
    float4 p1 = *(const float4*)(g_p + N1 + idx);
    float4 v;
    v.x = fmaxf(fmaf(p0.x + p1.x, sc, sh), 0.f);
    v.y = fmaxf(fmaf(p0.y + p1.y, sc, sh), 0.f);
    v.z = fmaxf(fmaf(p0.z + p1.z, sc, sh), 0.f);
    v.w = fmaxf(fmaf(p0.w + p1.w, sc, sh), 0.f);
    *(float4*)(g_w1 + idx) = v;
}

// ---------------------------------------------------------------------------
// K2: w2 = conv2_1x1(w1) + bias. Tile 64o x 64px, 128 thr, 8x4. (round-8)
// ---------------------------------------------------------------------------
__global__ __launch_bounds__(128) void k2_conv2(
        const float* __restrict__ w2w,
        const float* __restrict__ w2b) {
    __shared__ float As[64 * 68];
    __shared__ float Bs[64 * 64];

    const int tid = threadIdx.x;
    const int tx = tid & 15;
    const int ty = tid >> 4;
    const int px0 = blockIdx.x * 64;
    const int o0 = blockIdx.y * 64;
    const int b = blockIdx.z;

    {
        int k = tid & 63;
        int oh = tid >> 6;
#pragma unroll
        for (int r = 0; r < 32; ++r) {
            int o = 2 * r + oh;
            As[k * 68 + o] = (o0 + o < M2) ? w2w[(o0 + o) * CR + k] : 0.f;
        }
    }
    {
        int j = tid & 63;
        int kh = tid >> 6;
#pragma unroll
        for (int r = 0; r < 32; ++r) {
            int k = 2 * r + kh;
            Bs[k * 64 + j] = g_w1[(size_t)(b * CR + k) * HW + px0 + j];
        }
    }
    __syncthreads();

    float acc[8][4];
#pragma unroll
    for (int i = 0; i < 8; ++i)
#pragma unroll
        for (int u = 0; u < 4; ++u) acc[i][u] = 0.f;

#pragma unroll 8
    for (int k = 0; k < 64; ++k) {
        float4 a0 = *(const float4*)&As[k * 68 + ty * 8];
        float4 a1 = *(const float4*)&As[k * 68 + ty * 8 + 4];
        float4 bv = *(const float4*)&Bs[k * 64 + tx * 4];
        float av[8] = {a0.x, a0.y, a0.z, a0.w, a1.x, a1.y, a1.z, a1.w};
#pragma unroll
        for (int i = 0; i < 8; ++i) {
            acc[i][0] = fmaf(av[i], bv.x, acc[i][0]);
            acc[i][1] = fmaf(av[i], bv.y, acc[i][1]);
            acc[i][2] = fmaf(av[i], bv.z, acc[i][2]);
            acc[i][3] = fmaf(av[i], bv.w, acc[i][3]);
        }
    }

#pragma unroll
    for (int i = 0; i < 8; ++i) {
        int o = o0 + ty * 8 + i;
        if (o >= M2) continue;
        float bias = w2b[o];
        float4 v;
        v.x = acc[i][0] + bias;
        v.y = acc[i][1] + bias;
        v.z = acc[i][2] + bias;
        v.w = acc[i][3] + bias;
        *(float4*)(g_w2 + (size_t)(b * M2 + o) * HW + px0 + tx * 4) = v;
    }
}

// ---------------------------------------------------------------------------
// K3: involution reduce. Block = (8-row band, group, batch); 224 threads.
// Thread = 4 px x 8 ch: each weight LDG.128 feeds 32 FMAs (2x round-9),
// halving chip-wide weight-load count. xs layout [row][ch][64] -> pure-shift
// staging indexing (no divisions). Grid 448 blocks.
// ---------------------------------------------------------------------------
__global__ __launch_bounds__(224) void k3_involution(
        const float* __restrict__ x,
        float* __restrict__ out) {
    extern __shared__ float xs[];        // [14 rows][16 ch][64 cols]

    const int tid = threadIdx.x;
    const int h0 = blockIdx.x * 8;       // 7 bands
    const int g = blockIdx.y;
    const int b = blockIdx.z;

    // stage x: rows h0-3 .. h0+10, cols -3..60 (clipped). 64 iters exactly.
    const float* xg = x + (size_t)(b * CC + g * GC) * HW;
#pragma unroll 4
    for (int i = tid; i < XS_FLOATS; i += 224) {
        int row = i >> 10;               // 16*64 = 1024 per row
        int ch = (i >> 6) & 15;
        int col = i & 63;
        int hh = h0 - 3 + row;
        int ww = col - 3;
        float v = 0.f;
        if (hh >= 0 && hh < HH && (unsigned)ww < (unsigned)WW)
            v = xg[(size_t)ch * HW + hh * WW + ww];
        xs[i] = v;
    }
    __syncthreads();

    // mapping: q = px quad (14), rr = tid/14: r = rr&7 (8 rows), cgr = rr>>3
    const int q = tid % 14;
    const int rr = tid / 14;
    const int r = rr & 7;
    const int cgr = rr >> 3;             // 0/1 -> channels cgr*8 .. +7
    const int w0 = q * 4;
    const int h = h0 + r;

    const float* wg = g_w2 + ((size_t)(b * GG + g) * K2T) * HW + h * WW + w0;

    float acc[8][4];
#pragma unroll
    for (int c = 0; c < 8; ++c)
#pragma unroll
        for (int p = 0; p < 4; ++p) acc[c][p] = 0.f;

#pragma unroll
    for (int ki = 0; ki < KK; ++ki) {
        float4 wv[7];
#pragma unroll
        for (int kj = 0; kj < KK; ++kj)
            wv[kj] = *(const float4*)(wg + (size_t)(ki * KK + kj) * HW);
        const float* xrow = &xs[(r + ki) * 1024 + cgr * 8 * 64 + w0];
#pragma unroll
        for (int c = 0; c < 8; ++c) {
            const float* xr = xrow + c * 64;
            float4 xa = *(const float4*)(xr);
            float4 xb = *(const float4*)(xr + 4);
            float4 xc = *(const float4*)(xr + 8);
            float xw[12] = {xa.x, xa.y, xa.z, xa.w,
                            xb.x, xb.y, xb.z, xb.w,
                            xc.x, xc.y, xc.z, xc.w};
#pragma unroll
            for (int kj = 0; kj < KK; ++kj) {
                acc[c][0] = fmaf(wv[kj].x, xw[kj + 0], acc[c][0]);
                acc[c][1] = fmaf(wv[kj].y, xw[kj + 1], acc[c][1]);
                acc[c][2] = fmaf(wv[kj].z, xw[kj + 2], acc[c][2]);
                acc[c][3] = fmaf(wv[kj].w, xw[kj + 3], acc[c][3]);
            }
        }
    }

#pragma unroll
    for (int c = 0; c < 8; ++c) {
        float4 v = make_float4(acc[c][0], acc[c][1], acc[c][2], acc[c][3]);
        *(float4*)(out + (size_t)(b * CC + g * GC + cgr * 8 + c) * HW
                   + h * WW + w0) = v;
    }
}

// ---------------------------------------------------------------------------
extern "C" void kernel_launch(void* const* d_in, const int* in_sizes, int n_in,
                              void* d_out, int out_size) {
    const float* x     = (const float*)d_in[0];
    const float* w1w   = (const float*)d_in[1];
    const float* gamma = (const float*)d_in[2];
    const float* beta  = (const float*)d_in[3];
    const float* mean  = (const float*)d_in[4];
    const float* var   = (const float*)d_in[5];
    const float* w2w   = (const float*)d_in[6];
    const float* w2b   = (const float*)d_in[7];
    float* out = (float*)d_out;

    static bool attr_set = false;
    if (!attr_set) {
        cudaFuncSetAttribute(k3_involution,
                             cudaFuncAttributeMaxDynamicSharedMemorySize,
                             K3_SMEM_BYTES);
        attr_set = true;
    }

    dim3 g1(HW / 32, BB, 2);                    // 98 x 4 x 2 = 784
    k1a_partial<<<g1, 128>>>(x, w1w);

    k1b_bn_relu<<<(N1 / 4 + 255) / 256, 256>>>(gamma, beta, mean, var);

    dim3 g2(HW / 64, (M2 + 63) / 64, BB);       // 49 x 13 x 4 = 2548
    k2_conv2<<<g2, 128>>>(w2w, w2b);

    dim3 g3(HH / 8, GG, BB);                    // 7 x 16 x 4 = 448
    k3_involution<<<g3, 224, K3_SMEM_BYTES>>>(x, out);
}